// round 11
// baseline (speedup 1.0000x reference)
#include <cuda_runtime.h>
#include <math.h>

#define NN   302
#define TT   2048
#define TT4  512
#define KK   33
#define TEX  2080
#define NOD  16
#define DTs  0.2f
#define CROP 16
#define NTs  ((size_t)NN * TT)
#define NNP  312            // global list capacity
#define LCAP 128            // smem list capacity

#define CONV_BLOCKS (NN * 4)   // 1208: 128 thr x 4 outputs = 512 t per block
#define SPAR_BLOCKS 76         // 4 warps per 128-thr block, warp per row

// ---------------- scratch (static device globals; no allocs) ----------------
__device__ int   g_cnt[2 * NN];          // padded to multiple of 8
__device__ int   g_col[2][NN][NNP];      // stores PRE-SCALED offsets col*TT4
__device__ float g_valw[2][NN][NNP];

// select element j (0..7) from pair of float4s (compile-time j after unroll)
#define SEL(c, nx, j) ((j)==0?(c).x:(j)==1?(c).y:(j)==2?(c).z:(j)==3?(c).w: \
                       (j)==4?(nx).x:(j)==5?(nx).y:(j)==6?(nx).z:(nx).w)

// ============================================================================
// K_A: conv blocks  [0, CONV_BLOCKS): inline sensory + depthwise convs +
//      VAE sample + softplus (sections 2,3,4,5,8), R=4 outputs/thread.
//      spar blocks  [CONV_BLOCKS, +SPAR_BLOCKS): sparsify W_chem/W_elec.
// ============================================================================
__global__ void __launch_bounds__(128)
k_main(const float* __restrict__ fr,
       const float* __restrict__ odor,
       const float* __restrict__ Wenc,
       const float* __restrict__ benc,
       const float* __restrict__ mask,
       const float* __restrict__ eps,
       const float* __restrict__ Wmf, const float* __restrict__ Wms,
       const float* __restrict__ bmu,
       const float* __restrict__ Wlf, const float* __restrict__ Wls,
       const float* __restrict__ blv,
       const float* __restrict__ waff, const float* __restrict__ baff,
       const float* __restrict__ Wc, const float* __restrict__ We,
       float* __restrict__ out)
{
    const int tx = threadIdx.x;

    if (blockIdx.x >= CONV_BLOCKS) {
        // ---- sparsify: warp per matrix row, ballot compaction, pad to 8 ----
        // stores offsets col*TT4 (pre-scaled for the rec kernel)
        const int lane = tx & 31;
        const int m = (blockIdx.x - CONV_BLOCKS) * 4 + (tx >> 5);
        if (m >= NN) return;
        int c0 = 0, c1 = 0;
        for (int jb = 0; jb < NN; jb += 32) {
            const int j = jb + lane;
            float v = (j < NN) ? Wc[m * NN + j] : 0.0f;
            unsigned mk = __ballot_sync(0xffffffffu, v != 0.0f);
            if (v != 0.0f) {
                int p = c0 + __popc(mk & ((1u << lane) - 1u));
                g_col[0][m][p] = j * TT4; g_valw[0][m][p] = v;
            }
            c0 += __popc(mk);
            float w = (j < NN) ? We[m * NN + j] : 0.0f;
            mk = __ballot_sync(0xffffffffu, w != 0.0f);
            if (w != 0.0f) {
                int p = c1 + __popc(mk & ((1u << lane) - 1u));
                g_col[1][m][p] = j * TT4; g_valw[1][m][p] = w;
            }
            c1 += __popc(mk);
        }
        int c0p = (c0 + 7) & ~7;
        int c1p = (c1 + 7) & ~7;
        if (lane < c0p - c0) { g_col[0][m][c0 + lane] = 0; g_valw[0][m][c0 + lane] = 0.f; }
        if (lane < c1p - c1) { g_col[1][m][c1 + lane] = 0; g_valw[1][m][c1 + lane] = 0.f; }
        if (lane == 0) { g_cnt[m] = c0p; g_cnt[NN + m] = c1p; }
        return;
    }

    // ---------------- conv branch ----------------
    __shared__ float s_fr[560];          // 544 used (512 + 32 halo)
    __shared__ float s_se[560];
    __shared__ float4 s_w4[KK];
    const int n  = blockIdx.x >> 2;
    const int t0 = (blockIdx.x & 3) * 512;

    // Wenc row in registers (uniform across block -> broadcast loads)
    const float4* wep = (const float4*)(Wenc + n * NOD);
    const float4 w0 = __ldg(&wep[0]), w1 = __ldg(&wep[1]);
    const float4 w2 = __ldg(&wep[2]), w3 = __ldg(&wep[3]);
    const float msk = mask[n];
    const float be  = benc[n];

    // stage fr + compute sensory_extend inline (float4, 136 vecs)
    {
        float4* sfr4 = (float4*)s_fr;
        float4* sse4 = (float4*)s_se;
        const float4* fr4 = (const float4*)(fr + n * TEX + t0);
        for (int v = tx; v < 136; v += 128) {
            sfr4[v] = fr4[v];
            float4 acc = make_float4(0.f, 0.f, 0.f, 0.f);
#pragma unroll
            for (int o = 0; o < NOD; ++o) {
                float we;
                if (o < 8)  we = SEL(w0, w1, o);
                else        we = SEL(w2, w3, o - 8);
                const float4 ov = ((const float4*)(odor + o * TEX + t0))[v];
                acc.x = fmaf(ov.x, we, acc.x);
                acc.y = fmaf(ov.y, we, acc.y);
                acc.z = fmaf(ov.z, we, acc.z);
                acc.w = fmaf(ov.w, we, acc.w);
            }
            sse4[v] = make_float4(msk * (acc.x + be), msk * (acc.y + be),
                                  msk * (acc.z + be), msk * (acc.w + be));
        }
    }
    if (tx < KK)
        s_w4[tx] = make_float4(Wmf[n * KK + tx], Wms[n * KK + tx],
                               Wlf[n * KK + tx], Wls[n * KK + tx]);
    __syncthreads();

    const float4* f4 = (const float4*)s_fr;
    const float4* e4 = (const float4*)s_se;
    const int q = tx;
    float4 fc = f4[q], fn = f4[q + 1];
    float4 ec = e4[q], en = e4[q + 1];

    float am[4] = {0,0,0,0}, bm[4] = {0,0,0,0};
    float cl[4] = {0,0,0,0}, dl[4] = {0,0,0,0};

#pragma unroll 33
    for (int k = 0; k < KK; ++k) {
        const float4 w = s_w4[k];
        const int sub = k & 3;
#pragma unroll
        for (int r = 0; r < 4; ++r) {
            const float xf = SEL(fc, fn, sub + r);
            const float xe = SEL(ec, en, sub + r);
            am[r] = fmaf(xf, w.x, am[r]);
            bm[r] = fmaf(xe, w.y, bm[r]);
            cl[r] = fmaf(xf, w.z, cl[r]);
            dl[r] = fmaf(xe, w.w, dl[r]);
        }
        if (sub == 3) {
            fc = fn; fn = f4[q + (k >> 2) + 2];
            ec = en; en = e4[q + (k >> 2) + 2];
        }
    }

    const float bmu_n = bmu[n], blv_n = blv[n];
    const float wa = waff[n], ba = baff[n];
    const size_t idx4 = (size_t)n * TT4 + (t0 >> 2) + tx;
    const float4 ep = ((const float4*)eps)[idx4];

    float4 mu, lv, sv, ca;
    mu.x = am[0] + bm[0] + bmu_n;  mu.y = am[1] + bm[1] + bmu_n;
    mu.z = am[2] + bm[2] + bmu_n;  mu.w = am[3] + bm[3] + bmu_n;
    lv.x = cl[0] + dl[0] + blv_n;  lv.y = cl[1] + dl[1] + blv_n;
    lv.z = cl[2] + dl[2] + blv_n;  lv.w = cl[3] + dl[3] + blv_n;
    sv.x = fmaf(expf(0.5f * lv.x), ep.x, mu.x);
    sv.y = fmaf(expf(0.5f * lv.y), ep.y, mu.y);
    sv.z = fmaf(expf(0.5f * lv.z), ep.z, mu.z);
    sv.w = fmaf(expf(0.5f * lv.w), ep.w, mu.w);
    {
        float z;
        z = fmaf(wa, sv.x, ba); ca.x = fmaxf(z, 0.f) + log1pf(expf(-fabsf(z)));
        z = fmaf(wa, sv.y, ba); ca.y = fmaxf(z, 0.f) + log1pf(expf(-fabsf(z)));
        z = fmaf(wa, sv.z, ba); ca.z = fmaxf(z, 0.f) + log1pf(expf(-fabsf(z)));
        z = fmaf(wa, sv.w, ba); ca.w = fmaxf(z, 0.f) + log1pf(expf(-fabsf(z)));
    }
    ((float4*)(out + 2 * NTs))[idx4] = mu;
    ((float4*)(out + 3 * NTs))[idx4] = lv;
    ((float4*)(out + 4 * NTs))[idx4] = sv;
    ((float4*)(out + 5 * NTs))[idx4] = ca;
    ((float4*)(out + 8 * NTs))[idx4] = e4[q + (CROP >> 2)];
}

// ============================================================================
// K_B: ONE block per neuron (512 threads): sparse recurrent (full row,
//      1 float4/thread, MLP-8) + exponential IIR scan fused.
// ============================================================================
__global__ void __launch_bounds__(512)
k_epi(const float* __restrict__ bias,
      const float* __restrict__ tau,
      const float* __restrict__ ffull,
      const float* __restrict__ ctau,
      const float* __restrict__ scale,
      const float* __restrict__ shift,
      float* __restrict__ out)
{
    __shared__ float sbuf[TT + TT / 4];      // P(i) = i + (i>>2), stride-5
    __shared__ float sF[16], sE[16];
    __shared__ int   sc_off[LCAP], se_off[LCAP];
    __shared__ float sc_val[LCAP], se_val[LCAP];

    const int n  = blockIdx.x;
    const int tx = threadIdx.x;
    const int w    = tx >> 5;
    const int lane = tx & 31;

    // -------- Phase A: stage scan input + sparse lists --------
    const float* ca = out + 5 * NTs + (size_t)n * TT;
    for (int i = tx; i < TT; i += 512)
        sbuf[i + (i >> 2)] = ca[i];

    const int nc = g_cnt[n];
    const int ne = g_cnt[NN + n];
    if (tx < nc) { sc_off[tx] = g_col[0][n][tx]; sc_val[tx] = g_valw[0][n][tx]; }
    if (tx < ne) { se_off[tx] = g_col[1][n][tx]; se_val[tx] = g_valw[1][n][tx]; }
    __syncthreads();

    // -------- Phase B: recurrent, full row (t4 = tx) --------
    {
        const float4* sv4 = (const float4*)(out + 4 * NTs) + tx;
        float4 A = make_float4(0.f, 0.f, 0.f, 0.f);
        for (int i = 0; i < nc; i += 8) {
            float4 x[8];
#pragma unroll
            for (int u = 0; u < 8; ++u)
                x[u] = sv4[sc_off[i + u]];
#pragma unroll
            for (int u = 0; u < 8; ++u) {
                const float v = sc_val[i + u];
                A.x = fmaf(v, fmaxf(x[u].x, 0.f), A.x);
                A.y = fmaf(v, fmaxf(x[u].y, 0.f), A.y);
                A.z = fmaf(v, fmaxf(x[u].z, 0.f), A.z);
                A.w = fmaf(v, fmaxf(x[u].w, 0.f), A.w);
            }
        }
        for (int i = 0; i < ne; i += 8) {
            float4 x[8];
#pragma unroll
            for (int u = 0; u < 8; ++u)
                x[u] = sv4[se_off[i + u]];
#pragma unroll
            for (int u = 0; u < 8; ++u) {
                const float v = se_val[i + u];
                A.x = fmaf(v, x[u].x, A.x);  A.y = fmaf(v, x[u].y, A.y);
                A.z = fmaf(v, x[u].z, A.z);  A.w = fmaf(v, x[u].w, A.w);
            }
        }

        const float g  = DTs / tau[n];
        const float bi = bias[n];
        const size_t ridx = (size_t)n * TT4 + tx;
        float4 sen = ((const float4*)(out + 8 * NTs))[ridx];
        float4 sv  = ((const float4*)(out + 4 * NTs))[ridx];
        float4 rec, mun;
        rec.x = A.x + sen.x;  rec.y = A.y + sen.y;
        rec.z = A.z + sen.z;  rec.w = A.w + sen.w;
        mun.x = sv.x + g * (-sv.x + rec.x + bi);
        mun.y = sv.y + g * (-sv.y + rec.y + bi);
        mun.z = sv.z + g * (-sv.z + rec.z + bi);
        mun.w = sv.w + g * (-sv.w + rec.w + bi);
        ((float4*)(out + 7 * NTs))[ridx] = rec;
        ((float4*)(out + 0 * NTs))[ridx] = mun;
    }

    // -------- Phase C: exponential IIR scan (seg = 4 per thread) --------
    const float r = expf(-DTs / ctau[n]);
    float f = r; f *= f; f *= f;          // r^4

    const int base = tx * 5;              // P(4*tx)
    float e = 0.f;
#pragma unroll
    for (int j = 0; j < 4; ++j)
        e = fmaf(r, e, sbuf[base + j]);

    float F = f, E = e;
#pragma unroll
    for (int dd = 1; dd < 32; dd <<= 1) {
        float Fp = __shfl_up_sync(0xffffffffu, F, dd);
        float Ep = __shfl_up_sync(0xffffffffu, E, dd);
        if (lane >= dd) { E = fmaf(F, Ep, E); F = F * Fp; }
    }
    if (lane == 31) { sF[w] = F; sE[w] = E; }
    __syncthreads();

    float Fp = 1.f, Ep = 0.f;
    for (int qq = 0; qq < w; ++qq) {
        Ep = fmaf(sF[qq], Ep, sE[qq]);
        Fp = Fp * sF[qq];
    }

    const float init = (ffull[(size_t)n * TT] - shift[n]) / scale[n];
    const float x0   = init / r;          // m[-1] seed: m[0] = init + ca[0]
    const float pv   = fmaf(Fp, x0, Ep);

    float Fe = __shfl_up_sync(0xffffffffu, F, 1);
    float Ee = __shfl_up_sync(0xffffffffu, E, 1);
    float carry = (lane == 0) ? pv : fmaf(Fe, pv, Ee);

    float cacc = carry;
#pragma unroll
    for (int j = 0; j < 4; ++j) {
        cacc = fmaf(r, cacc, sbuf[base + j]);
        sbuf[base + j] = cacc;
    }
    __syncthreads();

    const float sc = scale[n], sh = shift[n];
    float* o6 = out + 6 * NTs + (size_t)n * TT;
    float* o1 = out + 1 * NTs + (size_t)n * TT;
    for (int i = tx; i < TT; i += 512) {
        float m = sbuf[i + (i >> 2)];
        o6[i] = m;
        o1[i] = fmaf(sc, m, sh);
    }
}

// ---------------- launch ----------------------------------------------------
extern "C" void kernel_launch(void* const* d_in, const int* in_sizes, int n_in,
                              void* d_out, int out_size)
{
    const float* fr    = (const float*)d_in[0];
    const float* ffull = (const float*)d_in[1];
    const float* odor  = (const float*)d_in[2];
    const float* eps   = (const float*)d_in[3];
    const float* Wenc  = (const float*)d_in[4];
    const float* benc  = (const float*)d_in[5];
    const float* mask  = (const float*)d_in[6];
    const float* Wmf   = (const float*)d_in[7];
    const float* Wms   = (const float*)d_in[8];
    const float* bmu   = (const float*)d_in[9];
    const float* Wlf   = (const float*)d_in[10];
    const float* Wls   = (const float*)d_in[11];
    const float* blv   = (const float*)d_in[12];
    const float* Wc    = (const float*)d_in[13];
    const float* We    = (const float*)d_in[14];
    const float* bias  = (const float*)d_in[15];
    const float* tau   = (const float*)d_in[16];
    const float* waff  = (const float*)d_in[17];
    const float* baff  = (const float*)d_in[18];
    const float* scale = (const float*)d_in[19];
    const float* shift = (const float*)d_in[20];
    const float* ctau  = (const float*)d_in[21];
    float* out = (float*)d_out;

    k_main<<<CONV_BLOCKS + SPAR_BLOCKS, 128>>>(fr, odor, Wenc, benc, mask, eps,
                                               Wmf, Wms, bmu, Wlf, Wls, blv,
                                               waff, baff, Wc, We, out);
    k_epi<<<NN, 512>>>(bias, tau, ffull, ctau, scale, shift, out);
}

// round 12
// speedup vs baseline: 1.0949x; 1.0949x over previous
#include <cuda_runtime.h>
#include <math.h>

#define NN   302
#define TT   2048
#define TT4  512
#define KK   33
#define TEX  2080
#define NOD  16
#define DTs  0.2f
#define CROP 16
#define NTs  ((size_t)NN * TT)
#define NNP  312            // global list capacity
#define LCAP 128            // smem list capacity

#define CONV_BLOCKS (NN * 4)   // 1208: 128 thr x 4 outputs = 512 t per block
#define SPAR_BLOCKS 76         // 4 warps per 128-thr block, warp per row

#define REC_BLOCKS  (NN * 4)   // 1208 quarter-row blocks (128 float4 each)
#define EPI_BLOCKS  (REC_BLOCKS + NN)   // + 302 scan blocks

// ---------------- scratch (static device globals; no allocs) ----------------
__device__ int   g_cnt[2 * NN];          // padded to multiple of 8
__device__ int   g_col[2][NN][NNP];      // PRE-SCALED offsets col*TT4
__device__ float g_valw[2][NN][NNP];

// select element j (0..7) from pair of float4s (compile-time j after unroll)
#define SEL(c, nx, j) ((j)==0?(c).x:(j)==1?(c).y:(j)==2?(c).z:(j)==3?(c).w: \
                       (j)==4?(nx).x:(j)==5?(nx).y:(j)==6?(nx).z:(nx).w)

// ============================================================================
// K_A: conv blocks [0, CONV_BLOCKS): inline sensory + depthwise convs +
//      VAE sample + softplus (sections 2,3,4,5,8), R=4 outputs/thread.
//      spar blocks [CONV_BLOCKS, +SPAR_BLOCKS): sparsify W_chem/W_elec.
// ============================================================================
__global__ void __launch_bounds__(128)
k_main(const float* __restrict__ fr,
       const float* __restrict__ odor,
       const float* __restrict__ Wenc,
       const float* __restrict__ benc,
       const float* __restrict__ mask,
       const float* __restrict__ eps,
       const float* __restrict__ Wmf, const float* __restrict__ Wms,
       const float* __restrict__ bmu,
       const float* __restrict__ Wlf, const float* __restrict__ Wls,
       const float* __restrict__ blv,
       const float* __restrict__ waff, const float* __restrict__ baff,
       const float* __restrict__ Wc, const float* __restrict__ We,
       float* __restrict__ out)
{
    const int tx = threadIdx.x;

    if (blockIdx.x >= CONV_BLOCKS) {
        // ---- sparsify: warp per matrix row, ballot compaction, pad to 8 ----
        const int lane = tx & 31;
        const int m = (blockIdx.x - CONV_BLOCKS) * 4 + (tx >> 5);
        if (m >= NN) return;
        int c0 = 0, c1 = 0;
        for (int jb = 0; jb < NN; jb += 32) {
            const int j = jb + lane;
            float v = (j < NN) ? Wc[m * NN + j] : 0.0f;
            unsigned mk = __ballot_sync(0xffffffffu, v != 0.0f);
            if (v != 0.0f) {
                int p = c0 + __popc(mk & ((1u << lane) - 1u));
                g_col[0][m][p] = j * TT4; g_valw[0][m][p] = v;
            }
            c0 += __popc(mk);
            float w = (j < NN) ? We[m * NN + j] : 0.0f;
            mk = __ballot_sync(0xffffffffu, w != 0.0f);
            if (w != 0.0f) {
                int p = c1 + __popc(mk & ((1u << lane) - 1u));
                g_col[1][m][p] = j * TT4; g_valw[1][m][p] = w;
            }
            c1 += __popc(mk);
        }
        int c0p = (c0 + 7) & ~7;
        int c1p = (c1 + 7) & ~7;
        if (lane < c0p - c0) { g_col[0][m][c0 + lane] = 0; g_valw[0][m][c0 + lane] = 0.f; }
        if (lane < c1p - c1) { g_col[1][m][c1 + lane] = 0; g_valw[1][m][c1 + lane] = 0.f; }
        if (lane == 0) { g_cnt[m] = c0p; g_cnt[NN + m] = c1p; }
        return;
    }

    // ---------------- conv branch ----------------
    __shared__ float s_fr[560];          // 544 used (512 + 32 halo)
    __shared__ float s_se[560];
    __shared__ float4 s_w4[KK];
    const int n  = blockIdx.x >> 2;
    const int t0 = (blockIdx.x & 3) * 512;

    const float4* wep = (const float4*)(Wenc + n * NOD);
    const float4 w0 = __ldg(&wep[0]), w1 = __ldg(&wep[1]);
    const float4 w2 = __ldg(&wep[2]), w3 = __ldg(&wep[3]);
    const float msk = mask[n];
    const float be  = benc[n];

    {
        float4* sfr4 = (float4*)s_fr;
        float4* sse4 = (float4*)s_se;
        const float4* fr4 = (const float4*)(fr + n * TEX + t0);
        for (int v = tx; v < 136; v += 128) {
            sfr4[v] = fr4[v];
            float4 acc = make_float4(0.f, 0.f, 0.f, 0.f);
#pragma unroll
            for (int o = 0; o < NOD; ++o) {
                float we;
                if (o < 8)  we = SEL(w0, w1, o);
                else        we = SEL(w2, w3, o - 8);
                const float4 ov = ((const float4*)(odor + o * TEX + t0))[v];
                acc.x = fmaf(ov.x, we, acc.x);
                acc.y = fmaf(ov.y, we, acc.y);
                acc.z = fmaf(ov.z, we, acc.z);
                acc.w = fmaf(ov.w, we, acc.w);
            }
            sse4[v] = make_float4(msk * (acc.x + be), msk * (acc.y + be),
                                  msk * (acc.z + be), msk * (acc.w + be));
        }
    }
    if (tx < KK)
        s_w4[tx] = make_float4(Wmf[n * KK + tx], Wms[n * KK + tx],
                               Wlf[n * KK + tx], Wls[n * KK + tx]);
    __syncthreads();

    const float4* f4 = (const float4*)s_fr;
    const float4* e4 = (const float4*)s_se;
    const int q = tx;
    float4 fc = f4[q], fn = f4[q + 1];
    float4 ec = e4[q], en = e4[q + 1];

    float am[4] = {0,0,0,0}, bm[4] = {0,0,0,0};
    float cl[4] = {0,0,0,0}, dl[4] = {0,0,0,0};

#pragma unroll 33
    for (int k = 0; k < KK; ++k) {
        const float4 w = s_w4[k];
        const int sub = k & 3;
#pragma unroll
        for (int r = 0; r < 4; ++r) {
            const float xf = SEL(fc, fn, sub + r);
            const float xe = SEL(ec, en, sub + r);
            am[r] = fmaf(xf, w.x, am[r]);
            bm[r] = fmaf(xe, w.y, bm[r]);
            cl[r] = fmaf(xf, w.z, cl[r]);
            dl[r] = fmaf(xe, w.w, dl[r]);
        }
        if (sub == 3) {
            fc = fn; fn = f4[q + (k >> 2) + 2];
            ec = en; en = e4[q + (k >> 2) + 2];
        }
    }

    const float bmu_n = bmu[n], blv_n = blv[n];
    const float wa = waff[n], ba = baff[n];
    const size_t idx4 = (size_t)n * TT4 + (t0 >> 2) + tx;
    const float4 ep = ((const float4*)eps)[idx4];

    float4 mu, lv, sv, ca;
    mu.x = am[0] + bm[0] + bmu_n;  mu.y = am[1] + bm[1] + bmu_n;
    mu.z = am[2] + bm[2] + bmu_n;  mu.w = am[3] + bm[3] + bmu_n;
    lv.x = cl[0] + dl[0] + blv_n;  lv.y = cl[1] + dl[1] + blv_n;
    lv.z = cl[2] + dl[2] + blv_n;  lv.w = cl[3] + dl[3] + blv_n;
    sv.x = fmaf(expf(0.5f * lv.x), ep.x, mu.x);
    sv.y = fmaf(expf(0.5f * lv.y), ep.y, mu.y);
    sv.z = fmaf(expf(0.5f * lv.z), ep.z, mu.z);
    sv.w = fmaf(expf(0.5f * lv.w), ep.w, mu.w);
    {
        float z;
        z = fmaf(wa, sv.x, ba); ca.x = fmaxf(z, 0.f) + log1pf(expf(-fabsf(z)));
        z = fmaf(wa, sv.y, ba); ca.y = fmaxf(z, 0.f) + log1pf(expf(-fabsf(z)));
        z = fmaf(wa, sv.z, ba); ca.z = fmaxf(z, 0.f) + log1pf(expf(-fabsf(z)));
        z = fmaf(wa, sv.w, ba); ca.w = fmaxf(z, 0.f) + log1pf(expf(-fabsf(z)));
    }
    ((float4*)(out + 2 * NTs))[idx4] = mu;
    ((float4*)(out + 3 * NTs))[idx4] = lv;
    ((float4*)(out + 4 * NTs))[idx4] = sv;
    ((float4*)(out + 5 * NTs))[idx4] = ca;
    ((float4*)(out + 8 * NTs))[idx4] = e4[q + (CROP >> 2)];
}

// ============================================================================
// K_B: blocks [0,1208): sparse recurrent, QUARTER-row per block (128 thr,
//      1 float4/thread, MLP-8, pre-scaled offsets);
//      blocks [1208,1510): exponential IIR scan, 128 thr, seg=16/thread.
// ============================================================================
__global__ void __launch_bounds__(128)
k_epi(const float* __restrict__ bias,
      const float* __restrict__ tau,
      const float* __restrict__ ffull,
      const float* __restrict__ ctau,
      const float* __restrict__ scale,
      const float* __restrict__ shift,
      float* __restrict__ out)
{
    const int tx = threadIdx.x;

    if (blockIdx.x >= REC_BLOCKS) {
        // ---------------- scan branch: 128 thr, seg = 16 ----------------
        __shared__ float sbuf[TT + TT / 16];     // P(i) = i + (i>>4), stride-17
        __shared__ float sF[4], sE[4];
        const int n    = blockIdx.x - REC_BLOCKS;
        const int w    = tx >> 5;
        const int lane = tx & 31;

        const float* ca = out + 5 * NTs + (size_t)n * TT;
        for (int i = tx; i < TT; i += 128)
            sbuf[i + (i >> 4)] = ca[i];
        __syncthreads();

        const float r = expf(-DTs / ctau[n]);
        float f = r; f *= f; f *= f; f *= f; f *= f;   // r^16

        const int base = tx * 17;                // P(16*tx)
        float e = 0.f;
#pragma unroll
        for (int j = 0; j < 16; ++j)
            e = fmaf(r, e, sbuf[base + j]);

        float F = f, E = e;
#pragma unroll
        for (int dd = 1; dd < 32; dd <<= 1) {
            float Fp = __shfl_up_sync(0xffffffffu, F, dd);
            float Ep = __shfl_up_sync(0xffffffffu, E, dd);
            if (lane >= dd) { E = fmaf(F, Ep, E); F = F * Fp; }
        }
        if (lane == 31) { sF[w] = F; sE[w] = E; }
        __syncthreads();

        float Fp = 1.f, Ep = 0.f;
        for (int qq = 0; qq < w; ++qq) {
            Ep = fmaf(sF[qq], Ep, sE[qq]);
            Fp = Fp * sF[qq];
        }

        const float init = (ffull[(size_t)n * TT] - shift[n]) / scale[n];
        const float x0   = init / r;             // m[-1] seed: m[0] = init + ca[0]
        const float pv   = fmaf(Fp, x0, Ep);

        float Fe = __shfl_up_sync(0xffffffffu, F, 1);
        float Ee = __shfl_up_sync(0xffffffffu, E, 1);
        float carry = (lane == 0) ? pv : fmaf(Fe, pv, Ee);

        float cacc = carry;
#pragma unroll
        for (int j = 0; j < 16; ++j) {
            cacc = fmaf(r, cacc, sbuf[base + j]);
            sbuf[base + j] = cacc;
        }
        __syncthreads();

        const float sc = scale[n], sh = shift[n];
        float* o6 = out + 6 * NTs + (size_t)n * TT;
        float* o1 = out + 1 * NTs + (size_t)n * TT;
        for (int i = tx; i < TT; i += 128) {
            float m = sbuf[i + (i >> 4)];
            o6[i] = m;
            o1[i] = fmaf(sc, m, sh);
        }
        return;
    }

    // ------------- recurrent branch: quarter-row, 1 float4/thread -----------
    __shared__ int   sc_off[LCAP], se_off[LCAP];
    __shared__ float sc_val[LCAP], se_val[LCAP];
    const int n  = blockIdx.x >> 2;
    const int t4 = (blockIdx.x & 3) * 128 + tx;

    const int nc = g_cnt[n];
    const int ne = g_cnt[NN + n];
    if (tx < nc) { sc_off[tx] = g_col[0][n][tx]; sc_val[tx] = g_valw[0][n][tx]; }
    if (tx < ne) { se_off[tx] = g_col[1][n][tx]; se_val[tx] = g_valw[1][n][tx]; }
    __syncthreads();

    const float4* sv4 = (const float4*)(out + 4 * NTs) + t4;

    float4 A = make_float4(0.f, 0.f, 0.f, 0.f);
    for (int i = 0; i < nc; i += 8) {
        float4 x[8];
#pragma unroll
        for (int u = 0; u < 8; ++u)
            x[u] = sv4[sc_off[i + u]];
#pragma unroll
        for (int u = 0; u < 8; ++u) {
            const float v = sc_val[i + u];
            A.x = fmaf(v, fmaxf(x[u].x, 0.f), A.x);
            A.y = fmaf(v, fmaxf(x[u].y, 0.f), A.y);
            A.z = fmaf(v, fmaxf(x[u].z, 0.f), A.z);
            A.w = fmaf(v, fmaxf(x[u].w, 0.f), A.w);
        }
    }
    for (int i = 0; i < ne; i += 8) {
        float4 x[8];
#pragma unroll
        for (int u = 0; u < 8; ++u)
            x[u] = sv4[se_off[i + u]];
#pragma unroll
        for (int u = 0; u < 8; ++u) {
            const float v = se_val[i + u];
            A.x = fmaf(v, x[u].x, A.x);  A.y = fmaf(v, x[u].y, A.y);
            A.z = fmaf(v, x[u].z, A.z);  A.w = fmaf(v, x[u].w, A.w);
        }
    }

    const float g  = DTs / tau[n];
    const float bi = bias[n];
    const size_t ridx = (size_t)n * TT4 + t4;
    float4 sen = ((const float4*)(out + 8 * NTs))[ridx];
    float4 sv  = ((const float4*)(out + 4 * NTs))[ridx];
    float4 rec, mun;
    rec.x = A.x + sen.x;  rec.y = A.y + sen.y;
    rec.z = A.z + sen.z;  rec.w = A.w + sen.w;
    mun.x = sv.x + g * (-sv.x + rec.x + bi);
    mun.y = sv.y + g * (-sv.y + rec.y + bi);
    mun.z = sv.z + g * (-sv.z + rec.z + bi);
    mun.w = sv.w + g * (-sv.w + rec.w + bi);
    ((float4*)(out + 7 * NTs))[ridx] = rec;
    ((float4*)(out + 0 * NTs))[ridx] = mun;
}

// ---------------- launch ----------------------------------------------------
extern "C" void kernel_launch(void* const* d_in, const int* in_sizes, int n_in,
                              void* d_out, int out_size)
{
    const float* fr    = (const float*)d_in[0];
    const float* ffull = (const float*)d_in[1];
    const float* odor  = (const float*)d_in[2];
    const float* eps   = (const float*)d_in[3];
    const float* Wenc  = (const float*)d_in[4];
    const float* benc  = (const float*)d_in[5];
    const float* mask  = (const float*)d_in[6];
    const float* Wmf   = (const float*)d_in[7];
    const float* Wms   = (const float*)d_in[8];
    const float* bmu   = (const float*)d_in[9];
    const float* Wlf   = (const float*)d_in[10];
    const float* Wls   = (const float*)d_in[11];
    const float* blv   = (const float*)d_in[12];
    const float* Wc    = (const float*)d_in[13];
    const float* We    = (const float*)d_in[14];
    const float* bias  = (const float*)d_in[15];
    const float* tau   = (const float*)d_in[16];
    const float* waff  = (const float*)d_in[17];
    const float* baff  = (const float*)d_in[18];
    const float* scale = (const float*)d_in[19];
    const float* shift = (const float*)d_in[20];
    const float* ctau  = (const float*)d_in[21];
    float* out = (float*)d_out;

    k_main<<<CONV_BLOCKS + SPAR_BLOCKS, 128>>>(fr, odor, Wenc, benc, mask, eps,
                                               Wmf, Wms, bmu, Wlf, Wls, blv,
                                               waff, baff, Wc, We, out);
    k_epi<<<EPI_BLOCKS, 128>>>(bias, tau, ffull, ctau, scale, shift, out);
}